// round 1
// baseline (speedup 1.0000x reference)
#include <cuda_runtime.h>
#include <cuda_bf16.h>

// Elementwise hard clip: out[i] = clamp(x[i], -0.5f, 0.5f)
// N = 32*2*1048576 = 67,108,864 fp32 elements. Pure HBM-streaming kernel.

#ifndef CLIP_LO
#define CLIP_LO (-0.5f)
#define CLIP_HI (0.5f)
#endif

__global__ __launch_bounds__(256) void clip_kernel_v4(
    const float4* __restrict__ in, float4* __restrict__ out, int n4)
{
    int stride = gridDim.x * blockDim.x;
    for (int i = blockIdx.x * blockDim.x + threadIdx.x; i < n4; i += stride) {
        float4 v = in[i];
        v.x = fminf(fmaxf(v.x, CLIP_LO), CLIP_HI);
        v.y = fminf(fmaxf(v.y, CLIP_LO), CLIP_HI);
        v.z = fminf(fmaxf(v.z, CLIP_LO), CLIP_HI);
        v.w = fminf(fmaxf(v.w, CLIP_LO), CLIP_HI);
        out[i] = v;
    }
}

// Scalar tail (not needed for this N, but keeps the kernel correct for any N).
__global__ void clip_kernel_tail(
    const float* __restrict__ in, float* __restrict__ out, int start, int n)
{
    int i = start + blockIdx.x * blockDim.x + threadIdx.x;
    if (i < n) {
        out[i] = fminf(fmaxf(in[i], CLIP_LO), CLIP_HI);
    }
}

extern "C" void kernel_launch(void* const* d_in, const int* in_sizes, int n_in,
                              void* d_out, int out_size)
{
    const float* x = (const float*)d_in[0];
    float* out = (float*)d_out;
    int n = in_sizes[0];

    int n4 = n / 4;
    const int threads = 256;
    // Fill the chip: 148 SMs, enough CTAs for a few grid-stride iterations each.
    int blocks = 148 * 8;
    int max_blocks = (n4 + threads - 1) / threads;
    if (blocks > max_blocks) blocks = max_blocks;
    if (blocks < 1) blocks = 1;

    clip_kernel_v4<<<blocks, threads>>>(
        (const float4*)x, (float4*)out, n4);

    int tail_start = n4 * 4;
    int tail = n - tail_start;
    if (tail > 0) {
        clip_kernel_tail<<<(tail + 255) / 256, 256>>>(x, out, tail_start, n);
    }
}

// round 2
// speedup vs baseline: 1.0240x; 1.0240x over previous
#include <cuda_runtime.h>
#include <cuda_bf16.h>

// Elementwise hard clip: out[i] = clamp(x[i], -0.5f, 0.5f)
// N = 67,108,864 fp32. Pure HBM stream: streaming cache hints + 2x unrolled
// front-batched 128-bit loads for max MLP.

#define CLIP_LO (-0.5f)
#define CLIP_HI (0.5f)

__device__ __forceinline__ float4 clip4(float4 v) {
    v.x = fminf(fmaxf(v.x, CLIP_LO), CLIP_HI);
    v.y = fminf(fmaxf(v.y, CLIP_LO), CLIP_HI);
    v.z = fminf(fmaxf(v.z, CLIP_LO), CLIP_HI);
    v.w = fminf(fmaxf(v.w, CLIP_LO), CLIP_HI);
    return v;
}

__global__ __launch_bounds__(256) void clip_kernel_v8(
    const float4* __restrict__ in, float4* __restrict__ out, int n4)
{
    const int tid = blockIdx.x * blockDim.x + threadIdx.x;
    const int stride = gridDim.x * blockDim.x;

    // Main loop: 2 independent float4 loads issued back-to-back (MLP), then
    // both stores. Streaming hints: no reuse, evict-first in L1/L2.
    int i = tid;
    const int stride2 = stride * 2;
    for (; i + stride < n4; i += stride2) {
        float4 a = __ldcs(in + i);
        float4 b = __ldcs(in + i + stride);
        a = clip4(a);
        b = clip4(b);
        __stcs(out + i, a);
        __stcs(out + i + stride, b);
    }
    if (i < n4) {
        float4 a = __ldcs(in + i);
        __stcs(out + i, clip4(a));
    }
}

// Scalar tail for N not divisible by 4 (not hit for this problem's N).
__global__ void clip_kernel_tail(
    const float* __restrict__ in, float* __restrict__ out, int start, int n)
{
    int i = start + blockIdx.x * blockDim.x + threadIdx.x;
    if (i < n) {
        out[i] = fminf(fmaxf(__ldcs(in + i), CLIP_LO), CLIP_HI);
    }
}

extern "C" void kernel_launch(void* const* d_in, const int* in_sizes, int n_in,
                              void* d_out, int out_size)
{
    const float* x = (const float*)d_in[0];
    float* out = (float*)d_out;
    int n = in_sizes[0];

    int n4 = n / 4;
    const int threads = 256;
    int blocks = 148 * 8;
    int max_blocks = (n4 + threads - 1) / threads;
    if (blocks > max_blocks) blocks = max_blocks;
    if (blocks < 1) blocks = 1;

    clip_kernel_v8<<<blocks, threads>>>(
        (const float4*)x, (float4*)out, n4);

    int tail_start = n4 * 4;
    int tail = n - tail_start;
    if (tail > 0) {
        clip_kernel_tail<<<(tail + 255) / 256, 256>>>(x, out, tail_start, n);
    }
}

// round 3
// speedup vs baseline: 1.0891x; 1.0636x over previous
#include <cuda_runtime.h>
#include <cuda_bf16.h>

// Elementwise hard clip: out[i] = clamp(x[i], -0.5f, 0.5f)
// N = 67,108,864 fp32. Contiguous per-CTA tiles for DRAM row locality,
// 4-deep front-batched 128-bit streaming loads/stores.

#define CLIP_LO (-0.5f)
#define CLIP_HI (0.5f)

__device__ __forceinline__ float4 clip4(float4 v) {
    v.x = fminf(fmaxf(v.x, CLIP_LO), CLIP_HI);
    v.y = fminf(fmaxf(v.y, CLIP_LO), CLIP_HI);
    v.z = fminf(fmaxf(v.z, CLIP_LO), CLIP_HI);
    v.w = fminf(fmaxf(v.w, CLIP_LO), CLIP_HI);
    return v;
}

// Each CTA owns a contiguous tile [start, start+chunk) of float4 elements and
// streams it front-to-back. Within an iteration, 4 independent LDG.128 are
// issued (offsets 0..3 * blockDim) before any store.
__global__ __launch_bounds__(256) void clip_kernel_tiled(
    const float4* __restrict__ in, float4* __restrict__ out,
    int n4, int chunk)
{
    const int bdim = blockDim.x;
    int start = blockIdx.x * chunk;
    int end = start + chunk;
    if (end > n4) end = n4;

    int i = start + threadIdx.x;
    const int step = bdim * 4;

    // Full 4-wide iterations
    for (; i + 3 * bdim < end; i += step) {
        float4 a = __ldcs(in + i);
        float4 b = __ldcs(in + i + bdim);
        float4 c = __ldcs(in + i + 2 * bdim);
        float4 d = __ldcs(in + i + 3 * bdim);
        a = clip4(a); b = clip4(b); c = clip4(c); d = clip4(d);
        __stcs(out + i,            a);
        __stcs(out + i + bdim,     b);
        __stcs(out + i + 2 * bdim, c);
        __stcs(out + i + 3 * bdim, d);
    }
    // Remainder within the tile
    for (; i < end; i += bdim) {
        float4 a = __ldcs(in + i);
        __stcs(out + i, clip4(a));
    }
}

// Scalar tail for N not divisible by 4 (not hit for this problem's N).
__global__ void clip_kernel_tail(
    const float* __restrict__ in, float* __restrict__ out, int start, int n)
{
    int i = start + blockIdx.x * blockDim.x + threadIdx.x;
    if (i < n) {
        out[i] = fminf(fmaxf(__ldcs(in + i), CLIP_LO), CLIP_HI);
    }
}

extern "C" void kernel_launch(void* const* d_in, const int* in_sizes, int n_in,
                              void* d_out, int out_size)
{
    const float* x = (const float*)d_in[0];
    float* out = (float*)d_out;
    int n = in_sizes[0];

    int n4 = n / 4;
    const int threads = 256;

    // 2048 CTAs: for n4 = 2^24, chunk = 8192 float4 = 128KB contiguous per CTA
    // (32 coalesced iterations). Divides evenly; generic path handles ragged n.
    int blocks = 2048;
    int chunk = (n4 + blocks - 1) / blocks;
    // Round chunk up to a multiple of threads so tiles stay warp-aligned.
    chunk = ((chunk + threads - 1) / threads) * threads;
    blocks = (n4 + chunk - 1) / chunk;
    if (blocks < 1) { blocks = 1; chunk = n4 > 0 ? n4 : 1; }

    clip_kernel_tiled<<<blocks, threads>>>(
        (const float4*)x, (float4*)out, n4, chunk);

    int tail_start = n4 * 4;
    int tail = n - tail_start;
    if (tail > 0) {
        clip_kernel_tail<<<(tail + 255) / 256, 256>>>(x, out, tail_start, n);
    }
}

// round 4
// speedup vs baseline: 1.1041x; 1.0137x over previous
#include <cuda_runtime.h>
#include <cuda_bf16.h>

// Elementwise hard clip: out[i] = clamp(x[i], -0.5f, 0.5f)
// N = 67,108,864 fp32. Contiguous per-CTA tiles, 8-deep front-batched
// 128-bit streaming loads then 8 stores (long R/W bursts to DRAM).

#define CLIP_LO (-0.5f)
#define CLIP_HI (0.5f)
#define BATCH 8

__device__ __forceinline__ float4 clip4(float4 v) {
    v.x = fminf(fmaxf(v.x, CLIP_LO), CLIP_HI);
    v.y = fminf(fmaxf(v.y, CLIP_LO), CLIP_HI);
    v.z = fminf(fmaxf(v.z, CLIP_LO), CLIP_HI);
    v.w = fminf(fmaxf(v.w, CLIP_LO), CLIP_HI);
    return v;
}

// Each CTA owns a contiguous tile [start, start+chunk) of float4 elements.
// Per iteration: BATCH independent LDG.128 (32KB/CTA read burst), clip,
// then BATCH STG.128 (32KB/CTA write burst).
__global__ __launch_bounds__(256) void clip_kernel_tiled8(
    const float4* __restrict__ in, float4* __restrict__ out,
    int n4, int chunk)
{
    const int bdim = blockDim.x;
    int start = blockIdx.x * chunk;
    int end = start + chunk;
    if (end > n4) end = n4;

    int i = start + threadIdx.x;
    const int step = bdim * BATCH;

    for (; i + (BATCH - 1) * bdim < end; i += step) {
        float4 v[BATCH];
#pragma unroll
        for (int j = 0; j < BATCH; j++)
            v[j] = __ldcs(in + i + j * bdim);
#pragma unroll
        for (int j = 0; j < BATCH; j++)
            v[j] = clip4(v[j]);
#pragma unroll
        for (int j = 0; j < BATCH; j++)
            __stcs(out + i + j * bdim, v[j]);
    }
    // Remainder within the tile
    for (; i < end; i += bdim) {
        float4 a = __ldcs(in + i);
        __stcs(out + i, clip4(a));
    }
}

// Scalar tail for N not divisible by 4 (not hit for this problem's N).
__global__ void clip_kernel_tail(
    const float* __restrict__ in, float* __restrict__ out, int start, int n)
{
    int i = start + blockIdx.x * blockDim.x + threadIdx.x;
    if (i < n) {
        out[i] = fminf(fmaxf(__ldcs(in + i), CLIP_LO), CLIP_HI);
    }
}

extern "C" void kernel_launch(void* const* d_in, const int* in_sizes, int n_in,
                              void* d_out, int out_size)
{
    const float* x = (const float*)d_in[0];
    float* out = (float*)d_out;
    int n = in_sizes[0];

    int n4 = n / 4;
    const int threads = 256;

    // 2048 CTAs: for n4 = 2^24, chunk = 8192 float4 = 128KB contiguous per CTA
    // (4 batched iterations of 2048 float4 each).
    int blocks = 2048;
    int chunk = (n4 + blocks - 1) / blocks;
    chunk = ((chunk + threads - 1) / threads) * threads;
    blocks = (n4 + chunk - 1) / chunk;
    if (blocks < 1) { blocks = 1; chunk = n4 > 0 ? n4 : 1; }

    clip_kernel_tiled8<<<blocks, threads>>>(
        (const float4*)x, (float4*)out, n4, chunk);

    int tail_start = n4 * 4;
    int tail = n - tail_start;
    if (tail > 0) {
        clip_kernel_tail<<<(tail + 255) / 256, 256>>>(x, out, tail_start, n);
    }
}

// round 5
// speedup vs baseline: 1.1203x; 1.0147x over previous
#include <cuda_runtime.h>
#include <cuda_bf16.h>

// Elementwise hard clip: out[i] = clamp(x[i], -0.5f, 0.5f)
// N = 67,108,864 fp32. Contiguous per-CTA tiles, 16-deep front-batched
// 128-bit streaming loads then 16 stores (64KB R / 64KB W bursts per CTA).

#define CLIP_LO (-0.5f)
#define CLIP_HI (0.5f)
#define BATCH 16

__device__ __forceinline__ float4 clip4(float4 v) {
    v.x = fminf(fmaxf(v.x, CLIP_LO), CLIP_HI);
    v.y = fminf(fmaxf(v.y, CLIP_LO), CLIP_HI);
    v.z = fminf(fmaxf(v.z, CLIP_LO), CLIP_HI);
    v.w = fminf(fmaxf(v.w, CLIP_LO), CLIP_HI);
    return v;
}

// Each CTA owns a contiguous tile [start, start+chunk) of float4 elements.
// Per iteration: BATCH independent LDG.128 (64KB/CTA read burst), clip,
// then BATCH STG.128 (64KB/CTA write burst).
__global__ __launch_bounds__(256) void clip_kernel_tiled16(
    const float4* __restrict__ in, float4* __restrict__ out,
    int n4, int chunk)
{
    const int bdim = blockDim.x;
    int start = blockIdx.x * chunk;
    int end = start + chunk;
    if (end > n4) end = n4;

    int i = start + threadIdx.x;
    const int step = bdim * BATCH;

    for (; i + (BATCH - 1) * bdim < end; i += step) {
        float4 v[BATCH];
#pragma unroll
        for (int j = 0; j < BATCH; j++)
            v[j] = __ldcs(in + i + j * bdim);
#pragma unroll
        for (int j = 0; j < BATCH; j++)
            v[j] = clip4(v[j]);
#pragma unroll
        for (int j = 0; j < BATCH; j++)
            __stcs(out + i + j * bdim, v[j]);
    }
    // Remainder within the tile
    for (; i < end; i += bdim) {
        float4 a = __ldcs(in + i);
        __stcs(out + i, clip4(a));
    }
}

// Scalar tail for N not divisible by 4 (not hit for this problem's N).
__global__ void clip_kernel_tail(
    const float* __restrict__ in, float* __restrict__ out, int start, int n)
{
    int i = start + blockIdx.x * blockDim.x + threadIdx.x;
    if (i < n) {
        out[i] = fminf(fmaxf(__ldcs(in + i), CLIP_LO), CLIP_HI);
    }
}

extern "C" void kernel_launch(void* const* d_in, const int* in_sizes, int n_in,
                              void* d_out, int out_size)
{
    const float* x = (const float*)d_in[0];
    float* out = (float*)d_out;
    int n = in_sizes[0];

    int n4 = n / 4;
    const int threads = 256;

    // 2048 CTAs: for n4 = 2^24, chunk = 8192 float4 = 128KB contiguous per CTA
    // (2 batched iterations of 4096 float4 each).
    int blocks = 2048;
    int chunk = (n4 + blocks - 1) / blocks;
    chunk = ((chunk + threads - 1) / threads) * threads;
    blocks = (n4 + chunk - 1) / chunk;
    if (blocks < 1) { blocks = 1; chunk = n4 > 0 ? n4 : 1; }

    clip_kernel_tiled16<<<blocks, threads>>>(
        (const float4*)x, (float4*)out, n4, chunk);

    int tail_start = n4 * 4;
    int tail = n - tail_start;
    if (tail > 0) {
        clip_kernel_tail<<<(tail + 255) / 256, 256>>>(x, out, tail_start, n);
    }
}